// round 3
// baseline (speedup 1.0000x reference)
#include <cuda_runtime.h>
#include <cstdint>

#define Bsz 4
#define Hsz 16
#define Ssz 2048
#define Dsz 128
#define BM 128
#define BN 64
#define NW 8
#define NT 256
#define QSTR 132   // banks (4g+t4): conflict-free fragment loads
#define KSTR 132
#define VSTR 136   // banks (8*t4+g): conflict-free fragment loads
#define PSTR 68
#define NEG_INF -1e30f

struct Smem {
  float Q[BM][QSTR];      // tf32 bit patterns, pre-scaled by 1/sqrt(D)
  float K[BN][KSTR];      // tf32 bit patterns
  float V[BN][VSTR];      // tf32 bit patterns
  float P[NW][16][PSTR];  // tf32 bit patterns (per-warp softmax probs)
};

__device__ __forceinline__ uint32_t f2tf(float x) {
  uint32_t r;
  asm("cvt.rna.tf32.f32 %0, %1;" : "=r"(r) : "f"(x));
  return r;
}
__device__ __forceinline__ uint32_t fbits(float x) { return __float_as_uint(x); }

__device__ __forceinline__ void mma_tf32(float* d, const uint32_t* a, const uint32_t* b) {
  asm volatile(
      "mma.sync.aligned.m16n8k8.row.col.f32.tf32.tf32.f32 "
      "{%0,%1,%2,%3}, {%4,%5,%6,%7}, {%8,%9}, {%0,%1,%2,%3};"
      : "+f"(d[0]), "+f"(d[1]), "+f"(d[2]), "+f"(d[3])
      : "r"(a[0]), "r"(a[1]), "r"(a[2]), "r"(a[3]), "r"(b[0]), "r"(b[1]));
}

__global__ __launch_bounds__(NT, 1) void fa_fwd(
    const float* __restrict__ gq, const float* __restrict__ gk,
    const float* __restrict__ gv, float* __restrict__ gout) {
  extern __shared__ Smem sm[];
  Smem& s = sm[0];

  const int bh = blockIdx.y;
  const int qt = gridDim.x - 1 - blockIdx.x;  // heavy (long-causal) tiles first
  const int m0 = qt * BM;
  const size_t base = (size_t)bh * Ssz * Dsz;
  const float* q = gq + base;
  const float* k = gk + base;
  const float* v = gv + base;
  float* out = gout + base;

  const int tid  = threadIdx.x;
  const int warp = tid >> 5;
  const int lane = tid & 31;
  const int g    = lane >> 2;  // groupID 0..7
  const int t4   = lane & 3;   // thread-in-group 0..3

  const float scl = 0.08838834764831845f;  // 1/sqrt(128)

  // ---- Load Q tile (pre-scale, cvt to tf32) ----
  for (int i = tid; i < BM * (Dsz / 4); i += NT) {
    int r = i >> 5;
    int c = (i & 31) * 4;
    float4 qv = *(const float4*)&q[(size_t)(m0 + r) * Dsz + c];
    s.Q[r][c + 0] = __uint_as_float(f2tf(qv.x * scl));
    s.Q[r][c + 1] = __uint_as_float(f2tf(qv.y * scl));
    s.Q[r][c + 2] = __uint_as_float(f2tf(qv.z * scl));
    s.Q[r][c + 3] = __uint_as_float(f2tf(qv.w * scl));
  }

  // Each warp owns one 16-row m-tile: rows [warp*16, warp*16+16)
  float o[16][4];                 // 16 d-tiles x c-frag
  float mi[2] = {NEG_INF, NEG_INF};
  float li[2] = {0.f, 0.f};
#pragma unroll
  for (int b = 0; b < 16; b++)
#pragma unroll
    for (int c = 0; c < 4; c++) o[b][c] = 0.f;

  const int tmax = 2 * qt + 1;  // k-tiles [0, tmax], BN=BM/2

  for (int t = 0; t <= tmax; t++) {
    const int n0 = t * BN;
    __syncthreads();
    // ---- Load K,V tiles (cvt to tf32) ----
    for (int i = tid; i < BN * (Dsz / 4); i += NT) {
      int r = i >> 5;
      int c = (i & 31) * 4;
      float4 kv = *(const float4*)&k[(size_t)(n0 + r) * Dsz + c];
      s.K[r][c + 0] = __uint_as_float(f2tf(kv.x));
      s.K[r][c + 1] = __uint_as_float(f2tf(kv.y));
      s.K[r][c + 2] = __uint_as_float(f2tf(kv.z));
      s.K[r][c + 3] = __uint_as_float(f2tf(kv.w));
      float4 vv = *(const float4*)&v[(size_t)(n0 + r) * Dsz + c];
      s.V[r][c + 0] = __uint_as_float(f2tf(vv.x));
      s.V[r][c + 1] = __uint_as_float(f2tf(vv.y));
      s.V[r][c + 2] = __uint_as_float(f2tf(vv.z));
      s.V[r][c + 3] = __uint_as_float(f2tf(vv.w));
    }
    __syncthreads();

    // ---- S = Q @ K^T : 1 m-tile x 8 n-tiles, K-dim 128 in 16 steps ----
    float sa[8][4];
#pragma unroll
    for (int b = 0; b < 8; b++)
#pragma unroll
      for (int c = 0; c < 4; c++) sa[b][c] = 0.f;

#pragma unroll
    for (int kt = 0; kt < 16; kt++) {
      const int kk = kt * 8;
      uint32_t afr[4];
      const int r = warp * 16 + g;
      afr[0] = fbits(s.Q[r][kk + t4]);
      afr[1] = fbits(s.Q[r + 8][kk + t4]);
      afr[2] = fbits(s.Q[r][kk + t4 + 4]);
      afr[3] = fbits(s.Q[r + 8][kk + t4 + 4]);
#pragma unroll
      for (int nt = 0; nt < 8; nt++) {
        uint32_t bfr[2];
        bfr[0] = fbits(s.K[nt * 8 + g][kk + t4]);
        bfr[1] = fbits(s.K[nt * 8 + g][kk + t4 + 4]);
        mma_tf32(sa[nt], afr, bfr);
      }
    }

    // ---- mask + online softmax per row-half ----
    const bool needmask = (n0 + BN - 1) > m0;
#pragma unroll
    for (int rr = 0; rr < 2; rr++) {
      const int grow = m0 + warp * 16 + rr * 8 + g;
      if (needmask) {
#pragma unroll
        for (int nt = 0; nt < 8; nt++) {
          int col = n0 + nt * 8 + 2 * t4;
          if (col > grow)     sa[nt][rr * 2 + 0] = NEG_INF;
          if (col + 1 > grow) sa[nt][rr * 2 + 1] = NEG_INF;
        }
      }
      float mx = NEG_INF;
#pragma unroll
      for (int nt = 0; nt < 8; nt++) {
        mx = fmaxf(mx, sa[nt][rr * 2 + 0]);
        mx = fmaxf(mx, sa[nt][rr * 2 + 1]);
      }
      mx = fmaxf(mx, __shfl_xor_sync(0xffffffffu, mx, 1));
      mx = fmaxf(mx, __shfl_xor_sync(0xffffffffu, mx, 2));

      float mnew  = fmaxf(mi[rr], mx);
      float alpha = __expf(mi[rr] - mnew);
      float rs = 0.f;
#pragma unroll
      for (int nt = 0; nt < 8; nt++) {
        float p0 = __expf(sa[nt][rr * 2 + 0] - mnew);
        float p1 = __expf(sa[nt][rr * 2 + 1] - mnew);
        sa[nt][rr * 2 + 0] = p0;
        sa[nt][rr * 2 + 1] = p1;
        rs += p0 + p1;
      }
      rs += __shfl_xor_sync(0xffffffffu, rs, 1);
      rs += __shfl_xor_sync(0xffffffffu, rs, 2);

      li[rr] = li[rr] * alpha + rs;
      mi[rr] = mnew;
#pragma unroll
      for (int dt = 0; dt < 16; dt++) {
        o[dt][rr * 2 + 0] *= alpha;
        o[dt][rr * 2 + 1] *= alpha;
      }
      // stage P (tf32) for the PV mma
      const int prow = rr * 8 + g;
#pragma unroll
      for (int nt = 0; nt < 8; nt++) {
        float2 pp;
        pp.x = __uint_as_float(f2tf(sa[nt][rr * 2 + 0]));
        pp.y = __uint_as_float(f2tf(sa[nt][rr * 2 + 1]));
        *(float2*)&s.P[warp][prow][nt * 8 + 2 * t4] = pp;
      }
    }
    __syncwarp();

    // ---- O += P @ V : K-dim 64 in 8 steps, 16 d-tiles ----
#pragma unroll
    for (int kt = 0; kt < 8; kt++) {
      const int kk = kt * 8;
      uint32_t afr[4];
      afr[0] = fbits(s.P[warp][g][kk + t4]);
      afr[1] = fbits(s.P[warp][g + 8][kk + t4]);
      afr[2] = fbits(s.P[warp][g][kk + t4 + 4]);
      afr[3] = fbits(s.P[warp][g + 8][kk + t4 + 4]);
#pragma unroll
      for (int dt = 0; dt < 16; dt++) {
        uint32_t bfr[2];
        bfr[0] = fbits(s.V[kk + t4][dt * 8 + g]);
        bfr[1] = fbits(s.V[kk + t4 + 4][dt * 8 + g]);
        mma_tf32(o[dt], afr, bfr);
      }
    }
  }

  // ---- Epilogue: normalize, store ----
#pragma unroll
  for (int rr = 0; rr < 2; rr++) {
    const float inv = 1.0f / li[rr];
    const size_t rowaddr = (size_t)(m0 + warp * 16 + rr * 8 + g) * Dsz;
#pragma unroll
    for (int dt = 0; dt < 16; dt++) {
      float2 ov;
      ov.x = o[dt][rr * 2 + 0] * inv;
      ov.y = o[dt][rr * 2 + 1] * inv;
      *(float2*)&out[rowaddr + dt * 8 + 2 * t4] = ov;
    }
  }
}

extern "C" void kernel_launch(void* const* d_in, const int* in_sizes, int n_in,
                              void* d_out, int out_size) {
  const int qkv_elems = Bsz * Hsz * Ssz * Dsz;
  const float* ptrs[3] = {nullptr, nullptr, nullptr};
  int np = 0;
  for (int i = 0; i < n_in && np < 3; i++) {
    if (in_sizes[i] == qkv_elems) ptrs[np++] = (const float*)d_in[i];
  }

  size_t smem_bytes = sizeof(Smem);
  cudaFuncSetAttribute(fa_fwd, cudaFuncAttributeMaxDynamicSharedMemorySize,
                       (int)smem_bytes);

  dim3 grid(Ssz / BM, Bsz * Hsz);
  fa_fwd<<<grid, NT, smem_bytes>>>(ptrs[0], ptrs[1], ptrs[2], (float*)d_out);
}

// round 8
// speedup vs baseline: 3.1547x; 3.1547x over previous
#include <cuda_runtime.h>
#include <cuda_fp16.h>
#include <cstdint>

#define Bsz 4
#define Hsz 16
#define Ssz 2048
#define Dsz 128
#define BM 128
#define BN 64
#define NT 128
#define NEG_INF -1e30f

// smem byte offsets (all 1KB-aligned); rows: Q/K 256B, Vt/P 128B
#define SM_Q 0
#define SM_K0 32768
#define SM_K1 49152
#define SM_V0 65536
#define SM_V1 81920
#define SM_P 98304  // + warp*4096
#define SM_TOTAL 114688

// fp16 scratch (converted by prepass kernels each launch)
__device__ __half QhG[(size_t)Bsz * Hsz * Ssz * Dsz];  // [bh][m][d], pre-scaled
__device__ __half KhG[(size_t)Bsz * Hsz * Ssz * Dsz];  // [bh][n][d]
__device__ __half VtG[(size_t)Bsz * Hsz * Ssz * Dsz];  // [bh][d][n]  (transposed)

__device__ __forceinline__ uint32_t smem_u32(const void* p) {
  uint32_t a;
  asm("{ .reg .u64 t; cvta.to.shared.u64 t, %1; cvt.u32.u64 %0, t; }" : "=r"(a) : "l"(p));
  return a;
}
__device__ __forceinline__ uint32_t lds32(uint32_t a) {
  uint32_t v;
  asm volatile("ld.shared.b32 %0, [%1];" : "=r"(v) : "r"(a));
  return v;
}
__device__ __forceinline__ void sts32(uint32_t a, uint32_t v) {
  asm volatile("st.shared.b32 [%0], %1;" ::"r"(a), "r"(v) : "memory");
}
#define CP16(dst, src) \
  asm volatile("cp.async.cg.shared.global [%0], [%1], 16;" ::"r"(dst), "l"(src) : "memory")
#define CP_COMMIT() asm volatile("cp.async.commit_group;" ::: "memory")
#define CP_WAIT1() asm volatile("cp.async.wait_group 1;" ::: "memory")
#define CP_WAIT0() asm volatile("cp.async.wait_group 0;" ::: "memory")

__device__ __forceinline__ void mma_f16(float* d, const uint32_t* a, const uint32_t* b) {
  asm volatile(
      "mma.sync.aligned.m16n8k16.row.col.f32.f16.f16.f32 "
      "{%0,%1,%2,%3}, {%4,%5,%6,%7}, {%8,%9}, {%0,%1,%2,%3};"
      : "+f"(d[0]), "+f"(d[1]), "+f"(d[2]), "+f"(d[3])
      : "r"(a[0]), "r"(a[1]), "r"(a[2]), "r"(a[3]), "r"(b[0]), "r"(b[1]));
}

// ---------------- prepass: fp32 -> fp16 (Q scaled; V transposed) ----------------
__global__ void prep_qk(const float* __restrict__ q, const float* __restrict__ k) {
  const float scl = 0.08838834764831845f;  // 1/sqrt(128)
  size_t i = ((size_t)blockIdx.x * blockDim.x + threadIdx.x) * 4;
  float4 qv = *(const float4*)(q + i);
  float4 kv = *(const float4*)(k + i);
  __half2* qo = (__half2*)(QhG + i);
  qo[0] = __floats2half2_rn(qv.x * scl, qv.y * scl);
  qo[1] = __floats2half2_rn(qv.z * scl, qv.w * scl);
  __half2* ko = (__half2*)(KhG + i);
  ko[0] = __floats2half2_rn(kv.x, kv.y);
  ko[1] = __floats2half2_rn(kv.z, kv.w);
}

__global__ void prep_v(const float* __restrict__ v) {
  __shared__ float tile[32][33];
  const int bh = blockIdx.z;
  const int n0 = blockIdx.x * 32, d0 = blockIdx.y * 32;
  const float* vp = v + (size_t)bh * Ssz * Dsz;
  const int tx = threadIdx.x, ty = threadIdx.y;
#pragma unroll
  for (int j = 0; j < 32; j += 8) tile[ty + j][tx] = vp[(size_t)(n0 + ty + j) * Dsz + d0 + tx];
  __syncthreads();
  __half* vt = VtG + (size_t)bh * Dsz * Ssz;
#pragma unroll
  for (int j = 0; j < 32; j += 8)
    vt[(size_t)(d0 + ty + j) * Ssz + n0 + tx] = __float2half_rn(tile[tx][ty + j]);
}

// ---------------- K/Vt tile prefetch via cp.async (swizzled dst) ----------------
__device__ __forceinline__ void kv_fetch(uint32_t smb, const __half* Kg, const __half* Vg,
                                         int n0, int buf, int tid) {
  const uint32_t kb = smb + (buf ? SM_K1 : SM_K0);
  const uint32_t vb = smb + (buf ? SM_V1 : SM_V0);
#pragma unroll 4
  for (int i = tid; i < 1024; i += NT) {  // K: 64 rows x 16 chunks (256B/row)
    int r = i >> 4, c = i & 15;
    CP16(kb + r * 256 + ((c * 16) ^ ((r & 7) * 16)),
         (const void*)(Kg + (size_t)(n0 + r) * Dsz + c * 8));
  }
#pragma unroll 4
  for (int i = tid; i < 1024; i += NT) {  // Vt: 128 rows x 8 chunks (128B/row)
    int r = i >> 3, c = i & 7;
    CP16(vb + r * 128 + ((c * 16) ^ ((r & 7) * 16)),
         (const void*)(Vg + (size_t)r * Ssz + n0 + c * 8));
  }
}

__global__ __launch_bounds__(NT, 1) void fa_fp16(float* __restrict__ gout) {
  extern __shared__ __align__(16) char sm[];
  const uint32_t smb = smem_u32(sm);

  const int bh = blockIdx.y;
  const int qt = gridDim.x - 1 - blockIdx.x;  // heavy q-tiles first
  const int m0 = qt * BM;
  const __half* Qg = QhG + (size_t)bh * Ssz * Dsz;
  const __half* Kg = KhG + (size_t)bh * Ssz * Dsz;
  const __half* Vg = VtG + (size_t)bh * Dsz * Ssz;
  float* out = gout + (size_t)bh * Ssz * Dsz;

  const int tid = threadIdx.x;
  const int warp = tid >> 5;
  const int lane = tid & 31;
  const int g = lane >> 2;
  const int t4 = lane & 3;
  const uint32_t swx = (uint32_t)g << 2;  // XOR on col2 index (rows always ≡ g mod 8)

  // issue Q (128 rows x 16 chunks) + KV tile 0, one commit group
#pragma unroll 4
  for (int i = tid; i < 2048; i += NT) {
    int r = i >> 4, c = i & 15;
    CP16(smb + SM_Q + r * 256 + ((c * 16) ^ ((r & 7) * 16)),
         (const void*)(Qg + (size_t)(m0 + r) * Dsz + c * 8));
  }
  kv_fetch(smb, Kg, Vg, 0, 0, tid);
  CP_COMMIT();

  float o[2][16][4];
  float mi[4] = {NEG_INF, NEG_INF, NEG_INF, NEG_INF};
  float li[4] = {0.f, 0.f, 0.f, 0.f};
#pragma unroll
  for (int a = 0; a < 2; a++)
#pragma unroll
    for (int b = 0; b < 16; b++)
#pragma unroll
      for (int c = 0; c < 4; c++) o[a][b][c] = 0.f;

  const int tmax = 2 * qt + 1;
  const uint32_t pb = smb + SM_P + warp * 4096;

  for (int t = 0; t <= tmax; t++) {
    const int n0 = t * BN;
    if (t < tmax) {  // prefetch next tile, then wait for current
      kv_fetch(smb, Kg, Vg, (t + 1) * BN, (t + 1) & 1, tid);
      CP_COMMIT();
      CP_WAIT1();
    } else {
      CP_WAIT0();
    }
    __syncthreads();

    const uint32_t kb = smb + ((t & 1) ? SM_K1 : SM_K0);
    const uint32_t vb = smb + ((t & 1) ? SM_V1 : SM_V0);

    // ---- S = Q @ K^T : 2 m-tiles x 8 n-tiles, k16 x 8 steps ----
    float sa[2][8][4];
#pragma unroll
    for (int a = 0; a < 2; a++)
#pragma unroll
      for (int b = 0; b < 8; b++)
#pragma unroll
        for (int c = 0; c < 4; c++) sa[a][b][c] = 0.f;

#pragma unroll
    for (int kt = 0; kt < 8; kt++) {
      const uint32_t c0 = (uint32_t)(kt * 8 + t4);
      uint32_t afr[2][4];
#pragma unroll
      for (int mt = 0; mt < 2; mt++) {
        const uint32_t r = (uint32_t)(warp * 32 + mt * 16 + g);
        afr[mt][0] = lds32(smb + SM_Q + r * 256 + ((c0 ^ swx) << 2));
        afr[mt][1] = lds32(smb + SM_Q + (r + 8) * 256 + ((c0 ^ swx) << 2));
        afr[mt][2] = lds32(smb + SM_Q + r * 256 + (((c0 + 4) ^ swx) << 2));
        afr[mt][3] = lds32(smb + SM_Q + (r + 8) * 256 + (((c0 + 4) ^ swx) << 2));
      }
#pragma unroll
      for (int nt = 0; nt < 8; nt++) {
        const uint32_t kr = (uint32_t)(nt * 8 + g);
        uint32_t bfr[2];
        bfr[0] = lds32(kb + kr * 256 + ((c0 ^ swx) << 2));
        bfr[1] = lds32(kb + kr * 256 + (((c0 + 4) ^ swx) << 2));
        mma_f16(sa[0][nt], afr[0], bfr);
        mma_f16(sa[1][nt], afr[1], bfr);
      }
    }

    // ---- mask + online softmax per (mtile, row-half); P -> smem (fp16) ----
    const bool needmask = (n0 + BN - 1) > m0;
#pragma unroll
    for (int mt = 0; mt < 2; mt++) {
#pragma unroll
      for (int rr = 0; rr < 2; rr++) {
        const int st = mt * 2 + rr;
        const int grow = m0 + warp * 32 + mt * 16 + rr * 8 + g;
        if (needmask) {
#pragma unroll
          for (int nt = 0; nt < 8; nt++) {
            int col = n0 + nt * 8 + 2 * t4;
            if (col > grow) sa[mt][nt][rr * 2 + 0] = NEG_INF;
            if (col + 1 > grow) sa[mt][nt][rr * 2 + 1] = NEG_INF;
          }
        }
        float mx = NEG_INF;
#pragma unroll
        for (int nt = 0; nt < 8; nt++) {
          mx = fmaxf(mx, sa[mt][nt][rr * 2 + 0]);
          mx = fmaxf(mx, sa[mt][nt][rr * 2 + 1]);
        }
        mx = fmaxf(mx, __shfl_xor_sync(0xffffffffu, mx, 1));
        mx = fmaxf(mx, __shfl_xor_sync(0xffffffffu, mx, 2));

        const float mnew = fmaxf(mi[st], mx);
        const float alpha = __expf(mi[st] - mnew);
        float rs = 0.f;
#pragma unroll
        for (int nt = 0; nt < 8; nt++) {
          float p0 = __expf(sa[mt][nt][rr * 2 + 0] - mnew);
          float p1 = __expf(sa[mt][nt][rr * 2 + 1] - mnew);
          sa[mt][nt][rr * 2 + 0] = p0;
          sa[mt][nt][rr * 2 + 1] = p1;
          rs += p0 + p1;
        }
        rs += __shfl_xor_sync(0xffffffffu, rs, 1);
        rs += __shfl_xor_sync(0xffffffffu, rs, 2);

        li[st] = li[st] * alpha + rs;
        mi[st] = mnew;
        if (alpha != 1.0f) {  // skip rescale when running max unchanged
#pragma unroll
          for (int dt = 0; dt < 16; dt++) {
            o[mt][dt][rr * 2 + 0] *= alpha;
            o[mt][dt][rr * 2 + 1] *= alpha;
          }
        }
        const uint32_t prow = (uint32_t)(mt * 16 + rr * 8 + g);
#pragma unroll
        for (int nt = 0; nt < 8; nt++) {
          __half2 h = __floats2half2_rn(sa[mt][nt][rr * 2 + 0], sa[mt][nt][rr * 2 + 1]);
          sts32(pb + prow * 128 + ((((uint32_t)(nt * 4 + t4)) ^ swx) << 2),
                *(uint32_t*)&h);
        }
      }
    }
    __syncwarp();

    // ---- O += P @ Vt : k16 x 4 steps, 16 d-tiles, 2 m-tiles ----
#pragma unroll
    for (int kt = 0; kt < 4; kt++) {
      const uint32_t c0 = (uint32_t)(kt * 8 + t4);
      uint32_t afr[2][4];
#pragma unroll
      for (int mt = 0; mt < 2; mt++) {
        const uint32_t r = (uint32_t)(mt * 16 + g);
        afr[mt][0] = lds32(pb + r * 128 + ((c0 ^ swx) << 2));
        afr[mt][1] = lds32(pb + (r + 8) * 128 + ((c0 ^ swx) << 2));
        afr[mt][2] = lds32(pb + r * 128 + (((c0 + 4) ^ swx) << 2));
        afr[mt][3] = lds32(pb + (r + 8) * 128 + (((c0 + 4) ^ swx) << 2));
      }
#pragma unroll
      for (int dt = 0; dt < 16; dt++) {
        const uint32_t vr = (uint32_t)(dt * 8 + g);
        uint32_t bfr[2];
        bfr[0] = lds32(vb + vr * 128 + ((c0 ^ swx) << 2));
        bfr[1] = lds32(vb + vr * 128 + (((c0 + 4) ^ swx) << 2));
        mma_f16(o[0][dt], afr[0], bfr);
        mma_f16(o[1][dt], afr[1], bfr);
      }
    }
    __syncthreads();  // all warps done with this tile's K/Vt before overwrite
  }

  // ---- epilogue: normalize, store fp32 ----
#pragma unroll
  for (int mt = 0; mt < 2; mt++) {
#pragma unroll
    for (int rr = 0; rr < 2; rr++) {
      const float inv = 1.0f / li[mt * 2 + rr];
      const size_t rowaddr = (size_t)(m0 + warp * 32 + mt * 16 + rr * 8 + g) * Dsz;
#pragma unroll
      for (int dt = 0; dt < 16; dt++) {
        float2 ov;
        ov.x = o[mt][dt][rr * 2 + 0] * inv;
        ov.y = o[mt][dt][rr * 2 + 1] * inv;
        *(float2*)&out[rowaddr + dt * 8 + 2 * t4] = ov;
      }
    }
  }
}

extern "C" void kernel_launch(void* const* d_in, const int* in_sizes, int n_in,
                              void* d_out, int out_size) {
  const int qkv_elems = Bsz * Hsz * Ssz * Dsz;
  const float* ptrs[3] = {nullptr, nullptr, nullptr};
  int np = 0;
  for (int i = 0; i < n_in && np < 3; i++) {
    if (in_sizes[i] == qkv_elems) ptrs[np++] = (const float*)d_in[i];
  }

  // prepass: fp32 -> fp16 conversions (Q scaled, V transposed)
  prep_qk<<<qkv_elems / 4 / 256, 256>>>(ptrs[0], ptrs[1]);
  prep_v<<<dim3(Ssz / 32, Dsz / 32, Bsz * Hsz), dim3(32, 8)>>>(ptrs[2]);

  cudaFuncSetAttribute(fa_fp16, cudaFuncAttributeMaxDynamicSharedMemorySize, SM_TOTAL);
  dim3 grid(Ssz / BM, Bsz * Hsz);
  fa_fp16<<<grid, NT, SM_TOTAL>>>((float*)d_out);
}

// round 9
// speedup vs baseline: 3.1672x; 1.0039x over previous
#include <cuda_runtime.h>
#include <cuda_fp16.h>
#include <cstdint>

#define Bsz 4
#define Hsz 16
#define Ssz 2048
#define Dsz 128
#define BM 128
#define BN 64
#define NT 128
#define NEG_INF -1e30f

// smem byte offsets (all 1KB-aligned); rows: Q/K 256B, Vt/P 128B
#define SM_Q 0
#define SM_K0 32768
#define SM_K1 49152
#define SM_V0 65536
#define SM_V1 81920
#define SM_P 98304  // + warp*4096
#define SM_TOTAL 114688

// fp16 scratch (converted by prepass kernels each launch)
__device__ __half QhG[(size_t)Bsz * Hsz * Ssz * Dsz];  // [bh][m][d], pre-scaled
__device__ __half KhG[(size_t)Bsz * Hsz * Ssz * Dsz];  // [bh][n][d]
__device__ __half VtG[(size_t)Bsz * Hsz * Ssz * Dsz];  // [bh][d][n]  (transposed)

__device__ __forceinline__ uint32_t smem_u32(const void* p) {
  uint32_t a;
  asm("{ .reg .u64 t; cvta.to.shared.u64 t, %1; cvt.u32.u64 %0, t; }" : "=r"(a) : "l"(p));
  return a;
}
__device__ __forceinline__ uint32_t lds32(uint32_t a) {
  uint32_t v;
  asm volatile("ld.shared.b32 %0, [%1];" : "=r"(v) : "r"(a));
  return v;
}
__device__ __forceinline__ void sts32(uint32_t a, uint32_t v) {
  asm volatile("st.shared.b32 [%0], %1;" ::"r"(a), "r"(v) : "memory");
}
#define CP16(dst, src) \
  asm volatile("cp.async.cg.shared.global [%0], [%1], 16;" ::"r"(dst), "l"(src) : "memory")
#define CP_COMMIT() asm volatile("cp.async.commit_group;" ::: "memory")
#define CP_WAIT1() asm volatile("cp.async.wait_group 1;" ::: "memory")
#define CP_WAIT0() asm volatile("cp.async.wait_group 0;" ::: "memory")

__device__ __forceinline__ void mma_f16(float* d, const uint32_t* a, const uint32_t* b) {
  asm volatile(
      "mma.sync.aligned.m16n8k16.row.col.f32.f16.f16.f32 "
      "{%0,%1,%2,%3}, {%4,%5,%6,%7}, {%8,%9}, {%0,%1,%2,%3};"
      : "+f"(d[0]), "+f"(d[1]), "+f"(d[2]), "+f"(d[3])
      : "r"(a[0]), "r"(a[1]), "r"(a[2]), "r"(a[3]), "r"(b[0]), "r"(b[1]));
}

// ---------------- prepass: fp32 -> fp16 (Q scaled; V transposed) ----------------
__global__ void prep_qk(const float* __restrict__ q, const float* __restrict__ k) {
  const float scl = 0.08838834764831845f;  // 1/sqrt(128)
  size_t i = ((size_t)blockIdx.x * blockDim.x + threadIdx.x) * 4;
  float4 qv = *(const float4*)(q + i);
  float4 kv = *(const float4*)(k + i);
  __half2* qo = (__half2*)(QhG + i);
  qo[0] = __floats2half2_rn(qv.x * scl, qv.y * scl);
  qo[1] = __floats2half2_rn(qv.z * scl, qv.w * scl);
  __half2* ko = (__half2*)(KhG + i);
  ko[0] = __floats2half2_rn(kv.x, kv.y);
  ko[1] = __floats2half2_rn(kv.z, kv.w);
}

__global__ void prep_v(const float* __restrict__ v) {
  __shared__ float tile[32][33];
  const int bh = blockIdx.z;
  const int n0 = blockIdx.x * 32, d0 = blockIdx.y * 32;
  const float* vp = v + (size_t)bh * Ssz * Dsz;
  const int tx = threadIdx.x, ty = threadIdx.y;
#pragma unroll
  for (int j = 0; j < 32; j += 8) tile[ty + j][tx] = vp[(size_t)(n0 + ty + j) * Dsz + d0 + tx];
  __syncthreads();
  __half* vt = VtG + (size_t)bh * Dsz * Ssz;
#pragma unroll
  for (int j = 0; j < 32; j += 8)
    vt[(size_t)(d0 + ty + j) * Ssz + n0 + tx] = __float2half_rn(tile[tx][ty + j]);
}

// ---------------- K/Vt tile prefetch via cp.async (swizzled dst) ----------------
__device__ __forceinline__ void kv_fetch(uint32_t smb, const __half* Kg, const __half* Vg,
                                         int n0, int buf, int tid) {
  const uint32_t kb = smb + (buf ? SM_K1 : SM_K0);
  const uint32_t vb = smb + (buf ? SM_V1 : SM_V0);
#pragma unroll 4
  for (int i = tid; i < 1024; i += NT) {  // K: 64 rows x 16 chunks (256B/row)
    int r = i >> 4, c = i & 15;
    CP16(kb + r * 256 + ((c * 16) ^ ((r & 7) * 16)),
         (const void*)(Kg + (size_t)(n0 + r) * Dsz + c * 8));
  }
#pragma unroll 4
  for (int i = tid; i < 1024; i += NT) {  // Vt: 128 rows x 8 chunks (128B/row)
    int r = i >> 3, c = i & 7;
    CP16(vb + r * 128 + ((c * 16) ^ ((r & 7) * 16)),
         (const void*)(Vg + (size_t)r * Ssz + n0 + c * 8));
  }
}

__global__ __launch_bounds__(NT, 2) void fa_fp16(float* __restrict__ gout) {
  extern __shared__ __align__(16) char sm[];
  const uint32_t smb = smem_u32(sm);

  const int bh = blockIdx.y;
  const int qt = gridDim.x - 1 - blockIdx.x;  // heavy q-tiles first
  const int m0 = qt * BM;
  const __half* Qg = QhG + (size_t)bh * Ssz * Dsz;
  const __half* Kg = KhG + (size_t)bh * Ssz * Dsz;
  const __half* Vg = VtG + (size_t)bh * Dsz * Ssz;
  float* out = gout + (size_t)bh * Ssz * Dsz;

  const int tid = threadIdx.x;
  const int warp = tid >> 5;
  const int lane = tid & 31;
  const int g = lane >> 2;
  const int t4 = lane & 3;
  const uint32_t swx = (uint32_t)g << 2;  // XOR on col2 index (rows always ≡ g mod 8)

  // issue Q (128 rows x 16 chunks) + KV tile 0, one commit group
#pragma unroll 4
  for (int i = tid; i < 2048; i += NT) {
    int r = i >> 4, c = i & 15;
    CP16(smb + SM_Q + r * 256 + ((c * 16) ^ ((r & 7) * 16)),
         (const void*)(Qg + (size_t)(m0 + r) * Dsz + c * 8));
  }
  kv_fetch(smb, Kg, Vg, 0, 0, tid);
  CP_COMMIT();

  float o[2][16][4];
  float mi[4] = {NEG_INF, NEG_INF, NEG_INF, NEG_INF};
  float li[4] = {0.f, 0.f, 0.f, 0.f};
#pragma unroll
  for (int a = 0; a < 2; a++)
#pragma unroll
    for (int b = 0; b < 16; b++)
#pragma unroll
      for (int c = 0; c < 4; c++) o[a][b][c] = 0.f;

  const int tmax = 2 * qt + 1;
  const uint32_t pb = smb + SM_P + warp * 4096;

  for (int t = 0; t <= tmax; t++) {
    const int n0 = t * BN;
    if (t < tmax) {  // prefetch next tile, then wait for current
      kv_fetch(smb, Kg, Vg, (t + 1) * BN, (t + 1) & 1, tid);
      CP_COMMIT();
      CP_WAIT1();
    } else {
      CP_WAIT0();
    }
    __syncthreads();

    const uint32_t kb = smb + ((t & 1) ? SM_K1 : SM_K0);
    const uint32_t vb = smb + ((t & 1) ? SM_V1 : SM_V0);

    // ---- S = Q @ K^T : 2 m-tiles x 8 n-tiles, k16 x 8 steps ----
    float sa[2][8][4];
#pragma unroll
    for (int a = 0; a < 2; a++)
#pragma unroll
      for (int b = 0; b < 8; b++)
#pragma unroll
        for (int c = 0; c < 4; c++) sa[a][b][c] = 0.f;

#pragma unroll
    for (int kt = 0; kt < 8; kt++) {
      const uint32_t c0 = (uint32_t)(kt * 8 + t4);
      uint32_t afr[2][4];
#pragma unroll
      for (int mt = 0; mt < 2; mt++) {
        const uint32_t r = (uint32_t)(warp * 32 + mt * 16 + g);
        afr[mt][0] = lds32(smb + SM_Q + r * 256 + ((c0 ^ swx) << 2));
        afr[mt][1] = lds32(smb + SM_Q + (r + 8) * 256 + ((c0 ^ swx) << 2));
        afr[mt][2] = lds32(smb + SM_Q + r * 256 + (((c0 + 4) ^ swx) << 2));
        afr[mt][3] = lds32(smb + SM_Q + (r + 8) * 256 + (((c0 + 4) ^ swx) << 2));
      }
#pragma unroll
      for (int nt = 0; nt < 8; nt++) {
        const uint32_t kr = (uint32_t)(nt * 8 + g);
        uint32_t bfr[2];
        bfr[0] = lds32(kb + kr * 256 + ((c0 ^ swx) << 2));
        bfr[1] = lds32(kb + kr * 256 + (((c0 + 4) ^ swx) << 2));
        mma_f16(sa[0][nt], afr[0], bfr);
        mma_f16(sa[1][nt], afr[1], bfr);
      }
    }

    // ---- mask + online softmax per (mtile, row-half); P -> smem (fp16) ----
    const bool needmask = (n0 + BN - 1) > m0;
#pragma unroll
    for (int mt = 0; mt < 2; mt++) {
#pragma unroll
      for (int rr = 0; rr < 2; rr++) {
        const int st = mt * 2 + rr;
        const int grow = m0 + warp * 32 + mt * 16 + rr * 8 + g;
        if (needmask) {
#pragma unroll
          for (int nt = 0; nt < 8; nt++) {
            int col = n0 + nt * 8 + 2 * t4;
            if (col > grow) sa[mt][nt][rr * 2 + 0] = NEG_INF;
            if (col + 1 > grow) sa[mt][nt][rr * 2 + 1] = NEG_INF;
          }
        }
        float mx = NEG_INF;
#pragma unroll
        for (int nt = 0; nt < 8; nt++) {
          mx = fmaxf(mx, sa[mt][nt][rr * 2 + 0]);
          mx = fmaxf(mx, sa[mt][nt][rr * 2 + 1]);
        }
        mx = fmaxf(mx, __shfl_xor_sync(0xffffffffu, mx, 1));
        mx = fmaxf(mx, __shfl_xor_sync(0xffffffffu, mx, 2));

        const float mnew = fmaxf(mi[st], mx);
        const float alpha = __expf(mi[st] - mnew);
        float rs = 0.f;
#pragma unroll
        for (int nt = 0; nt < 8; nt++) {
          float p0 = __expf(sa[mt][nt][rr * 2 + 0] - mnew);
          float p1 = __expf(sa[mt][nt][rr * 2 + 1] - mnew);
          sa[mt][nt][rr * 2 + 0] = p0;
          sa[mt][nt][rr * 2 + 1] = p1;
          rs += p0 + p1;
        }
        rs += __shfl_xor_sync(0xffffffffu, rs, 1);
        rs += __shfl_xor_sync(0xffffffffu, rs, 2);

        li[st] = li[st] * alpha + rs;
        mi[st] = mnew;
        if (alpha != 1.0f) {  // skip rescale when running max unchanged
#pragma unroll
          for (int dt = 0; dt < 16; dt++) {
            o[mt][dt][rr * 2 + 0] *= alpha;
            o[mt][dt][rr * 2 + 1] *= alpha;
          }
        }
        const uint32_t prow = (uint32_t)(mt * 16 + rr * 8 + g);
#pragma unroll
        for (int nt = 0; nt < 8; nt++) {
          __half2 h = __floats2half2_rn(sa[mt][nt][rr * 2 + 0], sa[mt][nt][rr * 2 + 1]);
          sts32(pb + prow * 128 + ((((uint32_t)(nt * 4 + t4)) ^ swx) << 2),
                *(uint32_t*)&h);
        }
      }
    }
    __syncwarp();

    // ---- O += P @ Vt : k16 x 4 steps, 16 d-tiles, 2 m-tiles ----
#pragma unroll
    for (int kt = 0; kt < 4; kt++) {
      const uint32_t c0 = (uint32_t)(kt * 8 + t4);
      uint32_t afr[2][4];
#pragma unroll
      for (int mt = 0; mt < 2; mt++) {
        const uint32_t r = (uint32_t)(mt * 16 + g);
        afr[mt][0] = lds32(pb + r * 128 + ((c0 ^ swx) << 2));
        afr[mt][1] = lds32(pb + (r + 8) * 128 + ((c0 ^ swx) << 2));
        afr[mt][2] = lds32(pb + r * 128 + (((c0 + 4) ^ swx) << 2));
        afr[mt][3] = lds32(pb + (r + 8) * 128 + (((c0 + 4) ^ swx) << 2));
      }
#pragma unroll
      for (int dt = 0; dt < 16; dt++) {
        const uint32_t vr = (uint32_t)(dt * 8 + g);
        uint32_t bfr[2];
        bfr[0] = lds32(vb + vr * 128 + ((c0 ^ swx) << 2));
        bfr[1] = lds32(vb + vr * 128 + (((c0 + 4) ^ swx) << 2));
        mma_f16(o[0][dt], afr[0], bfr);
        mma_f16(o[1][dt], afr[1], bfr);
      }
    }
    __syncthreads();  // all warps done with this tile's K/Vt before overwrite
  }

  // ---- epilogue: normalize, store fp32 ----
#pragma unroll
  for (int mt = 0; mt < 2; mt++) {
#pragma unroll
    for (int rr = 0; rr < 2; rr++) {
      const float inv = 1.0f / li[mt * 2 + rr];
      const size_t rowaddr = (size_t)(m0 + warp * 32 + mt * 16 + rr * 8 + g) * Dsz;
#pragma unroll
      for (int dt = 0; dt < 16; dt++) {
        float2 ov;
        ov.x = o[mt][dt][rr * 2 + 0] * inv;
        ov.y = o[mt][dt][rr * 2 + 1] * inv;
        *(float2*)&out[rowaddr + dt * 8 + 2 * t4] = ov;
      }
    }
  }
}

extern "C" void kernel_launch(void* const* d_in, const int* in_sizes, int n_in,
                              void* d_out, int out_size) {
  const int qkv_elems = Bsz * Hsz * Ssz * Dsz;
  const float* ptrs[3] = {nullptr, nullptr, nullptr};
  int np = 0;
  for (int i = 0; i < n_in && np < 3; i++) {
    if (in_sizes[i] == qkv_elems) ptrs[np++] = (const float*)d_in[i];
  }

  // prepass: fp32 -> fp16 conversions (Q scaled, V transposed)
  prep_qk<<<qkv_elems / 4 / 256, 256>>>(ptrs[0], ptrs[1]);
  prep_v<<<dim3(Ssz / 32, Dsz / 32, Bsz * Hsz), dim3(32, 8)>>>(ptrs[2]);

  cudaFuncSetAttribute(fa_fp16, cudaFuncAttributeMaxDynamicSharedMemorySize, SM_TOTAL);
  dim3 grid(Ssz / BM, Bsz * Hsz);
  fa_fp16<<<grid, NT, SM_TOTAL>>>((float*)d_out);
}

// round 11
// speedup vs baseline: 3.2622x; 1.0300x over previous
#include <cuda_runtime.h>
#include <cuda_fp16.h>
#include <cstdint>

#define Bsz 4
#define Hsz 16
#define Ssz 2048
#define Dsz 128
#define BM 128
#define BN 64
#define NT 128
#define NEG_INF -1e30f

// smem byte offsets; rows: Q/K 256B, Vt 128B
#define SM_Q 0
#define SM_K0 32768
#define SM_K1 49152
#define SM_V0 65536
#define SM_V1 81920
#define SM_TOTAL 98304   // 96 KB -> 2 CTAs/SM

// fp16 scratch (converted by prepass kernels each launch)
__device__ __half QhG[(size_t)Bsz * Hsz * Ssz * Dsz];  // [bh][m][d], pre-scaled
__device__ __half KhG[(size_t)Bsz * Hsz * Ssz * Dsz];  // [bh][n][d]
__device__ __half VtG[(size_t)Bsz * Hsz * Ssz * Dsz];  // [bh][d][n]  (transposed)

__device__ __forceinline__ uint32_t smem_u32(const void* p) {
  uint32_t a;
  asm("{ .reg .u64 t; cvta.to.shared.u64 t, %1; cvt.u32.u64 %0, t; }" : "=r"(a) : "l"(p));
  return a;
}
__device__ __forceinline__ uint32_t lds32(uint32_t a) {
  uint32_t v;
  asm volatile("ld.shared.b32 %0, [%1];" : "=r"(v) : "r"(a));
  return v;
}
#define CP16(dst, src) \
  asm volatile("cp.async.cg.shared.global [%0], [%1], 16;" ::"r"(dst), "l"(src) : "memory")
#define CP_COMMIT() asm volatile("cp.async.commit_group;" ::: "memory")
#define CP_WAIT1() asm volatile("cp.async.wait_group 1;" ::: "memory")
#define CP_WAIT0() asm volatile("cp.async.wait_group 0;" ::: "memory")

__device__ __forceinline__ void mma_f16(float* d, const uint32_t* a, const uint32_t* b) {
  asm volatile(
      "mma.sync.aligned.m16n8k16.row.col.f32.f16.f16.f32 "
      "{%0,%1,%2,%3}, {%4,%5,%6,%7}, {%8,%9}, {%0,%1,%2,%3};"
      : "+f"(d[0]), "+f"(d[1]), "+f"(d[2]), "+f"(d[3])
      : "r"(a[0]), "r"(a[1]), "r"(a[2]), "r"(a[3]), "r"(b[0]), "r"(b[1]));
}

// ---------------- prepass: fp32 -> fp16 (Q scaled; V transposed) ----------------
__global__ void prep_qk(const float* __restrict__ q, const float* __restrict__ k) {
  const float scl = 0.08838834764831845f;  // 1/sqrt(128)
  size_t i = ((size_t)blockIdx.x * blockDim.x + threadIdx.x) * 4;
  float4 qv = *(const float4*)(q + i);
  float4 kv = *(const float4*)(k + i);
  __half2* qo = (__half2*)(QhG + i);
  qo[0] = __floats2half2_rn(qv.x * scl, qv.y * scl);
  qo[1] = __floats2half2_rn(qv.z * scl, qv.w * scl);
  __half2* ko = (__half2*)(KhG + i);
  ko[0] = __floats2half2_rn(kv.x, kv.y);
  ko[1] = __floats2half2_rn(kv.z, kv.w);
}

__global__ void prep_v(const float* __restrict__ v) {
  __shared__ float tile[32][33];
  const int bh = blockIdx.z;
  const int n0 = blockIdx.x * 32, d0 = blockIdx.y * 32;
  const float* vp = v + (size_t)bh * Ssz * Dsz;
  const int tx = threadIdx.x, ty = threadIdx.y;
#pragma unroll
  for (int j = 0; j < 32; j += 8) tile[ty + j][tx] = vp[(size_t)(n0 + ty + j) * Dsz + d0 + tx];
  __syncthreads();
  __half* vt = VtG + (size_t)bh * Dsz * Ssz;
#pragma unroll
  for (int j = 0; j < 32; j += 8)
    vt[(size_t)(d0 + ty + j) * Ssz + n0 + tx] = __float2half_rn(tile[tx][ty + j]);
}

// ---------------- K/Vt tile prefetch via cp.async (swizzled dst) ----------------
__device__ __forceinline__ void kv_fetch(uint32_t smb, const __half* Kg, const __half* Vg,
                                         int n0, int buf, int tid) {
  const uint32_t kb = smb + (buf ? SM_K1 : SM_K0);
  const uint32_t vb = smb + (buf ? SM_V1 : SM_V0);
#pragma unroll 4
  for (int i = tid; i < 1024; i += NT) {  // K: 64 rows x 16 chunks (256B/row)
    int r = i >> 4, c = i & 15;
    CP16(kb + r * 256 + ((c * 16) ^ ((r & 7) * 16)),
         (const void*)(Kg + (size_t)(n0 + r) * Dsz + c * 8));
  }
#pragma unroll 4
  for (int i = tid; i < 1024; i += NT) {  // Vt: 128 rows x 8 chunks (128B/row)
    int r = i >> 3, c = i & 7;
    CP16(vb + r * 128 + ((c * 16) ^ ((r & 7) * 16)),
         (const void*)(Vg + (size_t)r * Ssz + n0 + c * 8));
  }
}

__global__ __launch_bounds__(NT, 2) void fa_fp16(float* __restrict__ gout) {
  extern __shared__ __align__(16) char sm[];
  const uint32_t smb = smem_u32(sm);

  const int bh = blockIdx.y;
  const int qt = gridDim.x - 1 - blockIdx.x;  // heavy q-tiles first
  const int m0 = qt * BM;
  const __half* Qg = QhG + (size_t)bh * Ssz * Dsz;
  const __half* Kg = KhG + (size_t)bh * Ssz * Dsz;
  const __half* Vg = VtG + (size_t)bh * Dsz * Ssz;
  float* out = gout + (size_t)bh * Ssz * Dsz;

  const int tid = threadIdx.x;
  const int warp = tid >> 5;
  const int lane = tid & 31;
  const int g = lane >> 2;
  const int t4 = lane & 3;
  const uint32_t swx = (uint32_t)g << 2;  // XOR on col2 index (rows always ≡ g mod 8)

  // issue Q (128 rows x 16 chunks) + KV tile 0, one commit group
#pragma unroll 4
  for (int i = tid; i < 2048; i += NT) {
    int r = i >> 4, c = i & 15;
    CP16(smb + SM_Q + r * 256 + ((c * 16) ^ ((r & 7) * 16)),
         (const void*)(Qg + (size_t)(m0 + r) * Dsz + c * 8));
  }
  kv_fetch(smb, Kg, Vg, 0, 0, tid);
  CP_COMMIT();

  float o[2][16][4];
  float mi[4] = {NEG_INF, NEG_INF, NEG_INF, NEG_INF};
  float li[4] = {0.f, 0.f, 0.f, 0.f};
#pragma unroll
  for (int a = 0; a < 2; a++)
#pragma unroll
    for (int b = 0; b < 16; b++)
#pragma unroll
      for (int c = 0; c < 4; c++) o[a][b][c] = 0.f;

  const int tmax = 2 * qt + 1;

  for (int t = 0; t <= tmax; t++) {
    const int n0 = t * BN;
    if (t < tmax) {  // prefetch next tile, then wait for current
      kv_fetch(smb, Kg, Vg, (t + 1) * BN, (t + 1) & 1, tid);
      CP_COMMIT();
      CP_WAIT1();
    } else {
      CP_WAIT0();
    }
    __syncthreads();

    const uint32_t kb = smb + ((t & 1) ? SM_K1 : SM_K0);
    const uint32_t vb = smb + ((t & 1) ? SM_V1 : SM_V0);

    // ---- S = Q @ K^T : 2 m-tiles x 8 n-tiles, k16 x 8 steps ----
    float sa[2][8][4];
#pragma unroll
    for (int a = 0; a < 2; a++)
#pragma unroll
      for (int b = 0; b < 8; b++)
#pragma unroll
        for (int c = 0; c < 4; c++) sa[a][b][c] = 0.f;

#pragma unroll
    for (int kt = 0; kt < 8; kt++) {
      const uint32_t c0 = (uint32_t)(kt * 8 + t4);
      uint32_t afr[2][4];
#pragma unroll
      for (int mt = 0; mt < 2; mt++) {
        const uint32_t r = (uint32_t)(warp * 32 + mt * 16 + g);
        afr[mt][0] = lds32(smb + SM_Q + r * 256 + ((c0 ^ swx) << 2));
        afr[mt][1] = lds32(smb + SM_Q + (r + 8) * 256 + ((c0 ^ swx) << 2));
        afr[mt][2] = lds32(smb + SM_Q + r * 256 + (((c0 + 4) ^ swx) << 2));
        afr[mt][3] = lds32(smb + SM_Q + (r + 8) * 256 + (((c0 + 4) ^ swx) << 2));
      }
#pragma unroll
      for (int nt = 0; nt < 8; nt++) {
        const uint32_t kr = (uint32_t)(nt * 8 + g);
        uint32_t bfr[2];
        bfr[0] = lds32(kb + kr * 256 + ((c0 ^ swx) << 2));
        bfr[1] = lds32(kb + kr * 256 + (((c0 + 4) ^ swx) << 2));
        mma_f16(sa[0][nt], afr[0], bfr);
        mma_f16(sa[1][nt], afr[1], bfr);
      }
    }

    // ---- mask + online softmax; P packed to half2 IN REGISTERS ----
    // C-fragment layout of S == A-fragment layout for the PV mma:
    //   ph[mt][nt][0] = half2(P[row g   ][2t4], P[row g   ][2t4+1])  (n-tile nt)
    //   ph[mt][nt][1] = half2(P[row g+8 ][2t4], P[row g+8 ][2t4+1])
    uint32_t ph[2][8][2];
    const bool needmask = (n0 + BN - 1) > m0;
#pragma unroll
    for (int mt = 0; mt < 2; mt++) {
#pragma unroll
      for (int rr = 0; rr < 2; rr++) {
        const int st = mt * 2 + rr;
        const int grow = m0 + warp * 32 + mt * 16 + rr * 8 + g;
        if (needmask) {
#pragma unroll
          for (int nt = 0; nt < 8; nt++) {
            int col = n0 + nt * 8 + 2 * t4;
            if (col > grow) sa[mt][nt][rr * 2 + 0] = NEG_INF;
            if (col + 1 > grow) sa[mt][nt][rr * 2 + 1] = NEG_INF;
          }
        }
        float mx = NEG_INF;
#pragma unroll
        for (int nt = 0; nt < 8; nt++) {
          mx = fmaxf(mx, sa[mt][nt][rr * 2 + 0]);
          mx = fmaxf(mx, sa[mt][nt][rr * 2 + 1]);
        }
        mx = fmaxf(mx, __shfl_xor_sync(0xffffffffu, mx, 1));
        mx = fmaxf(mx, __shfl_xor_sync(0xffffffffu, mx, 2));

        const float mnew = fmaxf(mi[st], mx);
        const float alpha = __expf(mi[st] - mnew);
        float rs = 0.f;
#pragma unroll
        for (int nt = 0; nt < 8; nt++) {
          float p0 = __expf(sa[mt][nt][rr * 2 + 0] - mnew);
          float p1 = __expf(sa[mt][nt][rr * 2 + 1] - mnew);
          rs += p0 + p1;
          __half2 h = __floats2half2_rn(p0, p1);
          ph[mt][nt][rr] = *(uint32_t*)&h;
        }
        rs += __shfl_xor_sync(0xffffffffu, rs, 1);
        rs += __shfl_xor_sync(0xffffffffu, rs, 2);

        li[st] = li[st] * alpha + rs;
        mi[st] = mnew;
        if (alpha != 1.0f) {  // skip rescale when running max unchanged
#pragma unroll
          for (int dt = 0; dt < 16; dt++) {
            o[mt][dt][rr * 2 + 0] *= alpha;
            o[mt][dt][rr * 2 + 1] *= alpha;
          }
        }
      }
    }

    // ---- O += P @ Vt : k16 x 4 steps (n-tiles 2kt,2kt+1), 16 d-tiles ----
#pragma unroll
    for (int kt = 0; kt < 4; kt++) {
      const uint32_t c0 = (uint32_t)(kt * 8 + t4);
      uint32_t afr[2][4];
#pragma unroll
      for (int mt = 0; mt < 2; mt++) {
        afr[mt][0] = ph[mt][2 * kt + 0][0];
        afr[mt][1] = ph[mt][2 * kt + 0][1];
        afr[mt][2] = ph[mt][2 * kt + 1][0];
        afr[mt][3] = ph[mt][2 * kt + 1][1];
      }
#pragma unroll
      for (int dt = 0; dt < 16; dt++) {
        const uint32_t vr = (uint32_t)(dt * 8 + g);
        uint32_t bfr[2];
        bfr[0] = lds32(vb + vr * 128 + ((c0 ^ swx) << 2));
        bfr[1] = lds32(vb + vr * 128 + (((c0 + 4) ^ swx) << 2));
        mma_f16(o[0][dt], afr[0], bfr);
        mma_f16(o[1][dt], afr[1], bfr);
      }
    }
    __syncthreads();  // all warps done with this tile's K/Vt before overwrite
  }

  // ---- epilogue: normalize, store fp32 ----
#pragma unroll
  for (int mt = 0; mt < 2; mt++) {
#pragma unroll
    for (int rr = 0; rr < 2; rr++) {
      const float inv = 1.0f / li[mt * 2 + rr];
      const size_t rowaddr = (size_t)(m0 + warp * 32 + mt * 16 + rr * 8 + g) * Dsz;
#pragma unroll
      for (int dt = 0; dt < 16; dt++) {
        float2 ov;
        ov.x = o[mt][dt][rr * 2 + 0] * inv;
        ov.y = o[mt][dt][rr * 2 + 1] * inv;
        *(float2*)&out[rowaddr + dt * 8 + 2 * t4] = ov;
      }
    }
  }
}

extern "C" void kernel_launch(void* const* d_in, const int* in_sizes, int n_in,
                              void* d_out, int out_size) {
  const int qkv_elems = Bsz * Hsz * Ssz * Dsz;
  const float* ptrs[3] = {nullptr, nullptr, nullptr};
  int np = 0;
  for (int i = 0; i < n_in && np < 3; i++) {
    if (in_sizes[i] == qkv_elems) ptrs[np++] = (const float*)d_in[i];
  }

  // prepass: fp32 -> fp16 conversions (Q scaled, V transposed)
  prep_qk<<<qkv_elems / 4 / 256, 256>>>(ptrs[0], ptrs[1]);
  prep_v<<<dim3(Ssz / 32, Dsz / 32, Bsz * Hsz), dim3(32, 8)>>>(ptrs[2]);

  cudaFuncSetAttribute(fa_fp16, cudaFuncAttributeMaxDynamicSharedMemorySize, SM_TOTAL);
  dim3 grid(Ssz / BM, Bsz * Hsz);
  fa_fp16<<<grid, NT, SM_TOTAL>>>((float*)d_out);
}